// round 5
// baseline (speedup 1.0000x reference)
#include <cuda_runtime.h>
#include <cstdint>

// ---------------- problem constants ----------------
#define B_   4
#define S_   12
#define N_   512
#define CIN  3
#define COUT 3
#define HID_ 64
#define HEADS_ 8
#define DH_  8
#define L_   2
#define E_   8192
#define BSN  (B_*S_*N_)          // 24576
#define BS_  (B_*S_)             // 48
#define SCALE_ 0.35355339059327373f

typedef unsigned long long u64;

// ---------------- f32x2 packed helpers (sm_100+) ----------------
__device__ __forceinline__ u64 pk2(float lo, float hi) {
    u64 r; asm("mov.b64 %0, {%1,%2};" : "=l"(r) : "f"(lo), "f"(hi)); return r;
}
__device__ __forceinline__ void upk2(u64 v, float& lo, float& hi) {
    asm("mov.b64 {%0,%1}, %2;" : "=f"(lo), "=f"(hi) : "l"(v));
}
__device__ __forceinline__ u64 fma2(u64 a, u64 b, u64 c) {
    u64 d; asm("fma.rn.f32x2 %0, %1, %2, %3;" : "=l"(d) : "l"(a), "l"(b), "l"(c)); return d;
}
__device__ __forceinline__ u64 mul2(u64 a, u64 b) {
    u64 d; asm("mul.rn.f32x2 %0, %1, %2;" : "=l"(d) : "l"(a), "l"(b)); return d;
}

// ---------------- device scratch ----------------
__device__ float g_h[BSN * HID_];
__device__ float g_q[BSN * HID_];
__device__ float g_k[BSN * HID_];
__device__ float g_v[BSN * HID_];
__device__ u64   g_mbits[N_ * 8];      // bitmask: row n, 512 key-bits

// ---------------- mask build (bitmask) ----------------
__global__ void mask_zero_kernel() {
    int i = blockIdx.x * blockDim.x + threadIdx.x;   // 4096
    g_mbits[i] = 0ull;
}

__global__ void mask_scatter_kernel(const int* __restrict__ ei) {
    int e = blockIdx.x * blockDim.x + threadIdx.x;
    if (e < E_) {
        int src = ei[e];
        int dst = ei[E_ + e];
        atomicOr(((unsigned int*)g_mbits) + src * 16 + (dst >> 5), 1u << (dst & 31));
    }
}

// ---------------- input projection ----------------
__global__ void in_proj_kernel(const float* __restrict__ x,
                               const float* __restrict__ Win,
                               const float* __restrict__ b_in) {
    int idx = blockIdx.x * blockDim.x + threadIdx.x;
    int j = idx & 63;
    int r = idx >> 6;
    const float* xr = x + r * 3;
    const float* w  = Win + j * 3;
    float s = b_in[j];
    s += xr[0] * w[0];
    s += xr[1] * w[1];
    s += xr[2] * w[2];
    g_h[idx] = s;
}

// ---------------- QKV projection: dot-product microkernel ----------------
// Both h and W consumed row-major (k-dim vectorized, f32x2 packed along k).
// Block: 256 threads, 64 rows x 64 cols. Thread tile 4r x 4j.
#define RS 68

__global__ __launch_bounds__(256) void qkv_proj_kernel(
    const float* __restrict__ Wq, const float* __restrict__ bq,
    const float* __restrict__ Wk, const float* __restrict__ bk,
    const float* __restrict__ Wv, const float* __restrict__ bv) {
    __shared__ float hR[64 * RS];
    __shared__ float wR[64 * RS];

    int tid = threadIdx.x;
    int r0 = blockIdx.x * 64;
    int mat = blockIdx.y;
    const float* W    = (mat == 0) ? Wq : (mat == 1) ? Wk : Wv;
    const float* bias = (mat == 0) ? bq : (mat == 1) ? bk : bv;
    float* out        = (mat == 0) ? g_q : (mat == 1) ? g_k : g_v;

    // stage h and W row-major (coalesced float4 copy, conflict-light)
#pragma unroll
    for (int i = 0; i < 4; i++) {
        int idx = tid + i * 256;            // 1024 float4 tasks
        int rr = idx >> 4, db = idx & 15;
        float4 hv = *(const float4*)(g_h + (size_t)(r0 + rr) * 64 + db * 4);
        *(float4*)(hR + rr * RS + db * 4) = hv;
        float4 wv = *(const float4*)(W + (size_t)rr * 64 + db * 4);
        *(float4*)(wR + rr * RS + db * 4) = wv;
    }
    __syncthreads();

    int cg = tid & 15;    // cols cg*4..+3
    int rg = tid >> 4;    // rows rg*4..+3
    const float* hp = hR + rg * 4 * RS;
    const float* wp = wR + cg * 4 * RS;

    u64 acc[4][4];
#pragma unroll
    for (int a = 0; a < 4; a++)
#pragma unroll
        for (int b = 0; b < 4; b++) acc[a][b] = 0ull;

#pragma unroll 4
    for (int kc = 0; kc < 16; kc++) {
        u64 hA[4], hB[4], wA[4], wB[4];
#pragma unroll
        for (int i = 0; i < 4; i++) {
            float4 hv = *(const float4*)(hp + i * RS + kc * 4);
            hA[i] = pk2(hv.x, hv.y);
            hB[i] = pk2(hv.z, hv.w);
        }
#pragma unroll
        for (int j = 0; j < 4; j++) {
            float4 wv = *(const float4*)(wp + j * RS + kc * 4);
            wA[j] = pk2(wv.x, wv.y);
            wB[j] = pk2(wv.z, wv.w);
        }
#pragma unroll
        for (int i = 0; i < 4; i++)
#pragma unroll
            for (int j = 0; j < 4; j++) {
                acc[i][j] = fma2(hA[i], wA[j], acc[i][j]);
                acc[i][j] = fma2(hB[i], wB[j], acc[i][j]);
            }
    }

    float4 b4 = *(const float4*)(bias + cg * 4);
#pragma unroll
    for (int i = 0; i < 4; i++) {
        float lo0, hi0, lo1, hi1, lo2, hi2, lo3, hi3;
        upk2(acc[i][0], lo0, hi0);
        upk2(acc[i][1], lo1, hi1);
        upk2(acc[i][2], lo2, hi2);
        upk2(acc[i][3], lo3, hi3);
        float4 o;
        o.x = lo0 + hi0 + b4.x;
        o.y = lo1 + hi1 + b4.y;
        o.z = lo2 + hi2 + b4.z;
        o.w = lo3 + hi3 + b4.w;
        *(float4*)(out + (size_t)(r0 + rg * 4 + i) * 64 + cg * 4) = o;
    }
}

// ---------------- sparse spatial attention: warp per query ----------------
// Lane l owns dims 2l..2l+1 (head = l>>2). K/V row reads are one coalesced
// 256B LDG.64 per key across the warp; dot finished with 2 shfl_xor within
// each 4-lane head group. grid (64, 48), 256 threads = 8 warps = 8 queries.
__global__ __launch_bounds__(256) void spatial_attn_kernel() {
    int lane = threadIdx.x & 31;
    int warp = threadIdx.x >> 5;
    int bs = blockIdx.y;
    int nq = blockIdx.x * 8 + warp;
    int d0 = lane * 2;

    const float* qb = g_q + ((size_t)bs * N_ + nq) * 64;
    u64 q2 = mul2(*(const u64*)(qb + d0), pk2(SCALE_, SCALE_));

    const float* kb = g_k + (size_t)bs * N_ * 64;
    const float* vb = g_v + (size_t)bs * N_ * 64;
    const u64* mrow = g_mbits + (size_t)nq * 8;

    float m_run = -1e30f, l_run = 0.f;
    u64 acc = 0ull;

#pragma unroll 1
    for (int c = 0; c < 8; c++) {
        u64 bits = mrow[c];            // uniform across warp
        int base = c * 64;
        while (bits) {
            int i = __ffsll((long long)bits) - 1;
            bits &= bits - 1;
            int m = base + i;
            u64 k2 = *(const u64*)(kb + (size_t)m * 64 + d0);
            u64 v2 = *(const u64*)(vb + (size_t)m * 64 + d0);
            float lo, hi;
            upk2(mul2(q2, k2), lo, hi);
            float pd = lo + hi;
            pd += __shfl_xor_sync(0xFFFFFFFFu, pd, 1);
            pd += __shfl_xor_sync(0xFFFFFFFFu, pd, 2);
            float mn = fmaxf(m_run, pd);
            float corr = __expf(m_run - mn);
            float p = __expf(pd - mn);
            l_run = fmaf(l_run, corr, p);
            acc = fma2(pk2(p, p), v2, mul2(acc, pk2(corr, corr)));
            m_run = mn;
        }
    }

    float o0, o1;
    if (l_run > 0.f) {
        upk2(acc, o0, o1);
        float inv = 1.f / l_run;
        o0 *= inv; o1 *= inv;
    } else {
        // no unmasked keys: softmax of all -1e9 -> uniform over 512
        o0 = o1 = 0.f;
        for (int m = 0; m < N_; m++) {
            float2 v = *(const float2*)(vb + (size_t)m * 64 + d0);
            o0 += v.x; o1 += v.y;
        }
        o0 *= (1.f / N_); o1 *= (1.f / N_);
    }
    *(u64*)(g_h + ((size_t)bs * N_ + nq) * 64 + d0) = pk2(o0, o1);
}

// ---------------- temporal attention (S=12) + fused final out-proj ----------
__global__ __launch_bounds__(128) void temporal_attn_kernel(
    const float* __restrict__ Wout, const float* __restrict__ bout,
    float* __restrict__ out, int last) {
    __shared__ float ksh[12 * 64];
    __shared__ float vsh[12 * 64];
    __shared__ float osh[64];
    int tid = threadIdx.x;
    int b = blockIdx.x >> 9;
    int n = blockIdx.x & 511;
    for (int i = tid; i < 12 * 64; i += 128) {
        int t = i >> 6, c = i & 63;
        size_t g = (((size_t)b * 12 + t) * N_ + n) * 64 + c;
        ksh[i] = g_k[g];
        vsh[i] = g_v[g];
    }
    __syncthreads();
    if (tid < 96) {
        int s = tid >> 3, hh = tid & 7;
        const float* qr = g_q + (((size_t)b * 12 + s) * N_ + n) * 64 + hh * 8;
        float qv[8];
#pragma unroll
        for (int d = 0; d < 8; d++) qv[d] = qr[d];
        float sc[12];
        float mx = -1e30f;
#pragma unroll
        for (int t = 0; t < 12; t++) {
            float dot = 0.f;
#pragma unroll
            for (int d = 0; d < 8; d++) dot = fmaf(qv[d], ksh[t * 64 + hh * 8 + d], dot);
            sc[t] = dot * SCALE_;
            mx = fmaxf(mx, sc[t]);
        }
        float l = 0.f;
#pragma unroll
        for (int t = 0; t < 12; t++) {
            sc[t] = __expf(sc[t] - mx);
            l += sc[t];
        }
        float acc[8];
#pragma unroll
        for (int d = 0; d < 8; d++) acc[d] = 0.f;
#pragma unroll
        for (int t = 0; t < 12; t++) {
#pragma unroll
            for (int d = 0; d < 8; d++)
                acc[d] = fmaf(sc[t], vsh[t * 64 + hh * 8 + d], acc[d]);
        }
        float inv = 1.f / l;
        float* orow = g_h + (((size_t)b * 12 + s) * N_ + n) * 64 + hh * 8;
#pragma unroll
        for (int d = 0; d < 8; d++) {
            float o = acc[d] * inv;
            orow[d] = o;
            if (last && s == 11) osh[hh * 8 + d] = o;
        }
    }
    if (last) {
        __syncthreads();
        if (tid < 3) {
            float s = bout[tid];
            const float* w = Wout + tid * 64;
#pragma unroll 16
            for (int d = 0; d < 64; d++) s = fmaf(osh[d], w[d], s);
            out[((size_t)b * N_ + n) * 3 + tid] = s;
        }
    }
}

// ---------------- launch ----------------
extern "C" void kernel_launch(void* const* d_in, const int* in_sizes, int n_in,
                              void* d_out, int out_size) {
    const float* x    = (const float*)d_in[0];
    const int*   ei   = (const int*)d_in[1];
    const float* Win  = (const float*)d_in[2];
    const float* b_in = (const float*)d_in[3];
    const float* Wqs  = (const float*)d_in[4];
    const float* bqs  = (const float*)d_in[5];
    const float* Wks  = (const float*)d_in[6];
    const float* bks  = (const float*)d_in[7];
    const float* Wvs  = (const float*)d_in[8];
    const float* bvs  = (const float*)d_in[9];
    const float* Wqt  = (const float*)d_in[10];
    const float* bqt  = (const float*)d_in[11];
    const float* Wkt  = (const float*)d_in[12];
    const float* bkt  = (const float*)d_in[13];
    const float* Wvt  = (const float*)d_in[14];
    const float* bvt  = (const float*)d_in[15];
    const float* Wout = (const float*)d_in[16];
    const float* bout = (const float*)d_in[17];
    float* out = (float*)d_out;

    mask_zero_kernel<<<16, 256>>>();
    mask_scatter_kernel<<<(E_ + 255) / 256, 256>>>(ei);
    in_proj_kernel<<<(BSN * HID_) / 256, 256>>>(x, Win, b_in);

    dim3 qkv_grid(BSN / 64, 3);
    for (int l = 0; l < L_; l++) {
        qkv_proj_kernel<<<qkv_grid, 256>>>(
            Wqs + l * 4096, bqs + l * 64,
            Wks + l * 4096, bks + l * 64,
            Wvs + l * 4096, bvs + l * 64);
        spatial_attn_kernel<<<dim3(64, BS_), 256>>>();
        qkv_proj_kernel<<<qkv_grid, 256>>>(
            Wqt + l * 4096, bqt + l * 64,
            Wkt + l * 4096, bkt + l * 64,
            Wvt + l * 4096, bvt + l * 64);
        temporal_attn_kernel<<<B_ * N_, 128>>>(Wout, bout, out, l == L_ - 1);
    }
}

// round 8
// speedup vs baseline: 1.4157x; 1.4157x over previous
#include <cuda_runtime.h>
#include <cstdint>

// ---------------- problem constants ----------------
#define B_   4
#define S_   12
#define N_   512
#define CIN  3
#define COUT 3
#define HID_ 64
#define HEADS_ 8
#define DH_  8
#define L_   2
#define E_   8192
#define BSN  (B_*S_*N_)          // 24576
#define BS_  (B_*S_)             // 48
#define SCALE_ 0.35355339059327373f

typedef unsigned long long u64;

// ---------------- f32x2 packed helpers (sm_100+) ----------------
__device__ __forceinline__ u64 pk2(float lo, float hi) {
    u64 r; asm("mov.b64 %0, {%1,%2};" : "=l"(r) : "f"(lo), "f"(hi)); return r;
}
__device__ __forceinline__ void upk2(u64 v, float& lo, float& hi) {
    asm("mov.b64 {%0,%1}, %2;" : "=f"(lo), "=f"(hi) : "l"(v));
}
__device__ __forceinline__ u64 fma2(u64 a, u64 b, u64 c) {
    u64 d; asm("fma.rn.f32x2 %0, %1, %2, %3;" : "=l"(d) : "l"(a), "l"(b), "l"(c)); return d;
}
__device__ __forceinline__ u64 mul2(u64 a, u64 b) {
    u64 d; asm("mul.rn.f32x2 %0, %1, %2;" : "=l"(d) : "l"(a), "l"(b)); return d;
}

// ---------------- device scratch ----------------
__device__ float g_h[BSN * HID_];
__device__ float g_q[BSN * HID_];
__device__ float g_k[BSN * HID_];
__device__ float g_v[BSN * HID_];
__device__ u64   g_mbits[N_ * 8];      // bitmask: row n, 512 key-bits

// ---------------- mask build (bitmask) ----------------
__global__ void mask_zero_kernel() {
    int i = blockIdx.x * blockDim.x + threadIdx.x;   // 4096
    g_mbits[i] = 0ull;
}

__global__ void mask_scatter_kernel(const int* __restrict__ ei) {
    int e = blockIdx.x * blockDim.x + threadIdx.x;
    if (e < E_) {
        int src = ei[e];
        int dst = ei[E_ + e];
        atomicOr(((unsigned int*)g_mbits) + src * 16 + (dst >> 5), 1u << (dst & 31));
    }
}

// ---------------- input projection ----------------
__global__ void in_proj_kernel(const float* __restrict__ x,
                               const float* __restrict__ Win,
                               const float* __restrict__ b_in) {
    int idx = blockIdx.x * blockDim.x + threadIdx.x;
    int j = idx & 63;
    int r = idx >> 6;
    const float* xr = x + r * 3;
    const float* w  = Win + j * 3;
    float s = b_in[j];
    s += xr[0] * w[0];
    s += xr[1] * w[1];
    s += xr[2] * w[2];
    g_h[idx] = s;
}

// ---------------- QKV projection: k-broadcast outer product ----------------
// 128 threads, 128 rows x 64 cols per block, thread tile 8x8.
// hT[d][r] stride 136 (broadcast, conflict-free). W stored split so the 8
// distinct 16B reads per warp stride 16B -> cover all 32 banks.
#define HT 136
#define WT 72
#define QKV_SMEM ((64*HT + 64*WT) * 4)

__global__ __launch_bounds__(128) void qkv_proj_kernel(
    const float* __restrict__ Wq, const float* __restrict__ bq,
    const float* __restrict__ Wk, const float* __restrict__ bk,
    const float* __restrict__ Wv, const float* __restrict__ bv) {
    extern __shared__ float smem[];
    float* hT = smem;              // [64][136]
    float* wT = smem + 64 * HT;    // [64][72]: cols 8g..8g+3 at d*72+g*4, 8g+4..+7 at +32

    int tid = threadIdx.x;
    int r0 = blockIdx.x * 128;
    int mat = blockIdx.y;
    const float* W    = (mat == 0) ? Wq : (mat == 1) ? Wk : Wv;
    const float* bias = (mat == 0) ? bq : (mat == 1) ? bk : bv;
    float* out        = (mat == 0) ? g_q : (mat == 1) ? g_k : g_v;

    // stage h transposed: 8192 elems / 128 threads
#pragma unroll
    for (int i = 0; i < 64; i++) {
        int idx = tid + i * 128;
        int r = idx >> 6, d = idx & 63;
        hT[d * HT + r] = g_h[(size_t)(r0 + r) * 64 + d];
    }
    // stage W split-layout: 4096 elems / 128 threads
#pragma unroll
    for (int i = 0; i < 32; i++) {
        int idx = tid + i * 128;
        int j = idx >> 6, d = idx & 63;
        int g = j >> 3, off = j & 7;
        wT[d * WT + ((off & 4) << 3) + g * 4 + (off & 3)] = W[idx];
    }
    __syncthreads();

    int cg = tid & 7;     // cols cg*8..+7
    int rg = tid >> 3;    // rows rg*8..+7

    u64 acc[4][8];
#pragma unroll
    for (int a = 0; a < 4; a++)
#pragma unroll
        for (int b = 0; b < 8; b++) acc[a][b] = 0ull;

    const float* hb = hT + rg * 8;
    const float* wb = wT + cg * 4;

#pragma unroll 8
    for (int d = 0; d < 64; d++) {
        float4 h0 = *(const float4*)(hb + d * HT);
        float4 h1 = *(const float4*)(hb + d * HT + 4);
        float4 w0 = *(const float4*)(wb + d * WT);
        float4 w1 = *(const float4*)(wb + d * WT + 32);
        u64 hp0 = pk2(h0.x, h0.y);
        u64 hp1 = pk2(h0.z, h0.w);
        u64 hp2 = pk2(h1.x, h1.y);
        u64 hp3 = pk2(h1.z, h1.w);
        u64 wd0 = pk2(w0.x, w0.x);
        u64 wd1 = pk2(w0.y, w0.y);
        u64 wd2 = pk2(w0.z, w0.z);
        u64 wd3 = pk2(w0.w, w0.w);
        u64 wd4 = pk2(w1.x, w1.x);
        u64 wd5 = pk2(w1.y, w1.y);
        u64 wd6 = pk2(w1.z, w1.z);
        u64 wd7 = pk2(w1.w, w1.w);
        acc[0][0] = fma2(hp0, wd0, acc[0][0]);
        acc[0][1] = fma2(hp0, wd1, acc[0][1]);
        acc[0][2] = fma2(hp0, wd2, acc[0][2]);
        acc[0][3] = fma2(hp0, wd3, acc[0][3]);
        acc[0][4] = fma2(hp0, wd4, acc[0][4]);
        acc[0][5] = fma2(hp0, wd5, acc[0][5]);
        acc[0][6] = fma2(hp0, wd6, acc[0][6]);
        acc[0][7] = fma2(hp0, wd7, acc[0][7]);
        acc[1][0] = fma2(hp1, wd0, acc[1][0]);
        acc[1][1] = fma2(hp1, wd1, acc[1][1]);
        acc[1][2] = fma2(hp1, wd2, acc[1][2]);
        acc[1][3] = fma2(hp1, wd3, acc[1][3]);
        acc[1][4] = fma2(hp1, wd4, acc[1][4]);
        acc[1][5] = fma2(hp1, wd5, acc[1][5]);
        acc[1][6] = fma2(hp1, wd6, acc[1][6]);
        acc[1][7] = fma2(hp1, wd7, acc[1][7]);
        acc[2][0] = fma2(hp2, wd0, acc[2][0]);
        acc[2][1] = fma2(hp2, wd1, acc[2][1]);
        acc[2][2] = fma2(hp2, wd2, acc[2][2]);
        acc[2][3] = fma2(hp2, wd3, acc[2][3]);
        acc[2][4] = fma2(hp2, wd4, acc[2][4]);
        acc[2][5] = fma2(hp2, wd5, acc[2][5]);
        acc[2][6] = fma2(hp2, wd6, acc[2][6]);
        acc[2][7] = fma2(hp2, wd7, acc[2][7]);
        acc[3][0] = fma2(hp3, wd0, acc[3][0]);
        acc[3][1] = fma2(hp3, wd1, acc[3][1]);
        acc[3][2] = fma2(hp3, wd2, acc[3][2]);
        acc[3][3] = fma2(hp3, wd3, acc[3][3]);
        acc[3][4] = fma2(hp3, wd4, acc[3][4]);
        acc[3][5] = fma2(hp3, wd5, acc[3][5]);
        acc[3][6] = fma2(hp3, wd6, acc[3][6]);
        acc[3][7] = fma2(hp3, wd7, acc[3][7]);
    }

    float bj[8];
#pragma unroll
    for (int j = 0; j < 8; j++) bj[j] = bias[cg * 8 + j];

#pragma unroll
    for (int i = 0; i < 4; i++) {
        float lo[8], hi[8];
#pragma unroll
        for (int j = 0; j < 8; j++) upk2(acc[i][j], lo[j], hi[j]);
        size_t rowA = (size_t)(r0 + rg * 8 + i * 2);
        float4 a0, a1, b0, b1;
        a0.x = lo[0] + bj[0]; a0.y = lo[1] + bj[1]; a0.z = lo[2] + bj[2]; a0.w = lo[3] + bj[3];
        a1.x = lo[4] + bj[4]; a1.y = lo[5] + bj[5]; a1.z = lo[6] + bj[6]; a1.w = lo[7] + bj[7];
        b0.x = hi[0] + bj[0]; b0.y = hi[1] + bj[1]; b0.z = hi[2] + bj[2]; b0.w = hi[3] + bj[3];
        b1.x = hi[4] + bj[4]; b1.y = hi[5] + bj[5]; b1.z = hi[6] + bj[6]; b1.w = hi[7] + bj[7];
        *(float4*)(out + rowA * 64 + cg * 8) = a0;
        *(float4*)(out + rowA * 64 + cg * 8 + 4) = a1;
        *(float4*)(out + (rowA + 1) * 64 + cg * 8) = b0;
        *(float4*)(out + (rowA + 1) * 64 + cg * 8 + 4) = b1;
    }
}

// ---------------- sparse spatial attention: warp per query ----------------
__global__ __launch_bounds__(256) void spatial_attn_kernel() {
    int lane = threadIdx.x & 31;
    int warp = threadIdx.x >> 5;
    int bs = blockIdx.y;
    int nq = blockIdx.x * 8 + warp;
    int d0 = lane * 2;

    const float* qb = g_q + ((size_t)bs * N_ + nq) * 64;
    u64 q2 = mul2(*(const u64*)(qb + d0), pk2(SCALE_, SCALE_));

    const float* kb = g_k + (size_t)bs * N_ * 64;
    const float* vb = g_v + (size_t)bs * N_ * 64;
    const u64* mrow = g_mbits + (size_t)nq * 8;

    float m_run = -1e30f, l_run = 0.f;
    u64 acc = 0ull;

#pragma unroll 1
    for (int c = 0; c < 8; c++) {
        u64 bits = mrow[c];            // uniform across warp
        int base = c * 64;
        while (bits) {
            int i = __ffsll((long long)bits) - 1;
            bits &= bits - 1;
            int m = base + i;
            u64 k2 = *(const u64*)(kb + (size_t)m * 64 + d0);
            u64 v2 = *(const u64*)(vb + (size_t)m * 64 + d0);
            float lo, hi;
            upk2(mul2(q2, k2), lo, hi);
            float pd = lo + hi;
            pd += __shfl_xor_sync(0xFFFFFFFFu, pd, 1);
            pd += __shfl_xor_sync(0xFFFFFFFFu, pd, 2);
            float mn = fmaxf(m_run, pd);
            float corr = __expf(m_run - mn);
            float p = __expf(pd - mn);
            l_run = fmaf(l_run, corr, p);
            acc = fma2(pk2(p, p), v2, mul2(acc, pk2(corr, corr)));
            m_run = mn;
        }
    }

    float o0, o1;
    if (l_run > 0.f) {
        upk2(acc, o0, o1);
        float inv = 1.f / l_run;
        o0 *= inv; o1 *= inv;
    } else {
        // no unmasked keys: softmax of all -1e9 -> uniform over 512
        o0 = o1 = 0.f;
        for (int m = 0; m < N_; m++) {
            float2 v = *(const float2*)(vb + (size_t)m * 64 + d0);
            o0 += v.x; o1 += v.y;
        }
        o0 *= (1.f / N_); o1 *= (1.f / N_);
    }
    *(u64*)(g_h + ((size_t)bs * N_ + nq) * 64 + d0) = pk2(o0, o1);
}

// ---------------- temporal attention (S=12) + fused final out-proj ----------
__global__ __launch_bounds__(128) void temporal_attn_kernel(
    const float* __restrict__ Wout, const float* __restrict__ bout,
    float* __restrict__ out, int last) {
    __shared__ float ksh[12 * 64];
    __shared__ float vsh[12 * 64];
    __shared__ float osh[64];
    int tid = threadIdx.x;
    int b = blockIdx.x >> 9;
    int n = blockIdx.x & 511;
    for (int i = tid; i < 12 * 64; i += 128) {
        int t = i >> 6, c = i & 63;
        size_t g = (((size_t)b * 12 + t) * N_ + n) * 64 + c;
        ksh[i] = g_k[g];
        vsh[i] = g_v[g];
    }
    __syncthreads();
    if (tid < 96) {
        int s = tid >> 3, hh = tid & 7;
        const float* qr = g_q + (((size_t)b * 12 + s) * N_ + n) * 64 + hh * 8;
        float qv[8];
#pragma unroll
        for (int d = 0; d < 8; d++) qv[d] = qr[d];
        float sc[12];
        float mx = -1e30f;
#pragma unroll
        for (int t = 0; t < 12; t++) {
            float dot = 0.f;
#pragma unroll
            for (int d = 0; d < 8; d++) dot = fmaf(qv[d], ksh[t * 64 + hh * 8 + d], dot);
            sc[t] = dot * SCALE_;
            mx = fmaxf(mx, sc[t]);
        }
        float l = 0.f;
#pragma unroll
        for (int t = 0; t < 12; t++) {
            sc[t] = __expf(sc[t] - mx);
            l += sc[t];
        }
        float acc[8];
#pragma unroll
        for (int d = 0; d < 8; d++) acc[d] = 0.f;
#pragma unroll
        for (int t = 0; t < 12; t++) {
#pragma unroll
            for (int d = 0; d < 8; d++)
                acc[d] = fmaf(sc[t], vsh[t * 64 + hh * 8 + d], acc[d]);
        }
        float inv = 1.f / l;
        float* orow = g_h + (((size_t)b * 12 + s) * N_ + n) * 64 + hh * 8;
#pragma unroll
        for (int d = 0; d < 8; d++) {
            float o = acc[d] * inv;
            orow[d] = o;
            if (last && s == 11) osh[hh * 8 + d] = o;
        }
    }
    if (last) {
        __syncthreads();
        if (tid < 3) {
            float s = bout[tid];
            const float* w = Wout + tid * 64;
#pragma unroll 16
            for (int d = 0; d < 64; d++) s = fmaf(osh[d], w[d], s);
            out[((size_t)b * N_ + n) * 3 + tid] = s;
        }
    }
}

// ---------------- launch ----------------
extern "C" void kernel_launch(void* const* d_in, const int* in_sizes, int n_in,
                              void* d_out, int out_size) {
    const float* x    = (const float*)d_in[0];
    const int*   ei   = (const int*)d_in[1];
    const float* Win  = (const float*)d_in[2];
    const float* b_in = (const float*)d_in[3];
    const float* Wqs  = (const float*)d_in[4];
    const float* bqs  = (const float*)d_in[5];
    const float* Wks  = (const float*)d_in[6];
    const float* bks  = (const float*)d_in[7];
    const float* Wvs  = (const float*)d_in[8];
    const float* bvs  = (const float*)d_in[9];
    const float* Wqt  = (const float*)d_in[10];
    const float* bqt  = (const float*)d_in[11];
    const float* Wkt  = (const float*)d_in[12];
    const float* bkt  = (const float*)d_in[13];
    const float* Wvt  = (const float*)d_in[14];
    const float* bvt  = (const float*)d_in[15];
    const float* Wout = (const float*)d_in[16];
    const float* bout = (const float*)d_in[17];
    float* out = (float*)d_out;

    static int smem_set = 0;
    if (!smem_set) {
        cudaFuncSetAttribute(qkv_proj_kernel,
                             cudaFuncAttributeMaxDynamicSharedMemorySize, QKV_SMEM);
        smem_set = 1;
    }

    mask_zero_kernel<<<16, 256>>>();
    mask_scatter_kernel<<<(E_ + 255) / 256, 256>>>(ei);
    in_proj_kernel<<<(BSN * HID_) / 256, 256>>>(x, Win, b_in);

    dim3 qkv_grid(BSN / 128, 3);
    for (int l = 0; l < L_; l++) {
        qkv_proj_kernel<<<qkv_grid, 128, QKV_SMEM>>>(
            Wqs + l * 4096, bqs + l * 64,
            Wks + l * 4096, bks + l * 64,
            Wvs + l * 4096, bvs + l * 64);
        spatial_attn_kernel<<<dim3(64, BS_), 256>>>();
        qkv_proj_kernel<<<qkv_grid, 128, QKV_SMEM>>>(
            Wqt + l * 4096, bqt + l * 64,
            Wkt + l * 4096, bkt + l * 64,
            Wvt + l * 4096, bvt + l * 64);
        temporal_attn_kernel<<<B_ * N_, 128>>>(Wout, bout, out, l == L_ - 1);
    }
}